// round 1
// baseline (speedup 1.0000x reference)
#include <cuda_runtime.h>

#define NU 200000
#define NI 100000
#define NT 300000           // NU + NI
#define D  64
#define NNZV 4000000
#define SCAN_N (NT + 1)
#define NB_SCAN ((SCAN_N + 1023) / 1024)   // 293

// -------- device scratch (static; no runtime allocation) --------
__device__ float g_emb0[(size_t)NT * D];   // 76.8 MB
__device__ float g_emb1[(size_t)NT * D];   // 76.8 MB
__device__ int   g_rowptr[NT + 1];
__device__ int   g_cursor[NT];
__device__ int   g_col[NNZV];
__device__ float g_val[NNZV];
__device__ int   g_bsum[NB_SCAN];

// -------- init: concat(user, item) -> g_emb0 --------
__global__ void init_k(const float4* __restrict__ u, const float4* __restrict__ it) {
    const int n = NT * D / 4;
    const int un = NU * D / 4;
    for (int i = blockIdx.x * blockDim.x + threadIdx.x; i < n; i += gridDim.x * blockDim.x) {
        float4 v = (i < un) ? u[i] : it[i - un];
        ((float4*)g_emb0)[i] = v;
    }
}

__global__ void zero_k() {
    for (int i = blockIdx.x * blockDim.x + threadIdx.x; i < SCAN_N; i += gridDim.x * blockDim.x)
        g_rowptr[i] = 0;
}

__global__ void hist_k(const int* __restrict__ rows) {
    for (int i = blockIdx.x * blockDim.x + threadIdx.x; i < NNZV; i += gridDim.x * blockDim.x)
        atomicAdd(&g_rowptr[rows[i] + 1], 1);
}

// -------- inclusive scan of g_rowptr (3 kernels) --------
__global__ void scan1_k() {
    __shared__ int s[1024];
    int tid = threadIdx.x;
    int gid = blockIdx.x * 1024 + tid;
    int v = (gid < SCAN_N) ? g_rowptr[gid] : 0;
    s[tid] = v;
    __syncthreads();
    for (int off = 1; off < 1024; off <<= 1) {
        int t = (tid >= off) ? s[tid - off] : 0;
        __syncthreads();
        s[tid] += t;
        __syncthreads();
    }
    if (gid < SCAN_N) g_rowptr[gid] = s[tid];
    if (tid == 1023) g_bsum[blockIdx.x] = s[1023];
}

__global__ void scan2_k() {
    __shared__ int s[512];
    int tid = threadIdx.x;
    int v = (tid < NB_SCAN) ? g_bsum[tid] : 0;
    s[tid] = v;
    __syncthreads();
    for (int off = 1; off < 512; off <<= 1) {
        int t = (tid >= off) ? s[tid - off] : 0;
        __syncthreads();
        s[tid] += t;
        __syncthreads();
    }
    if (tid < NB_SCAN) g_bsum[tid] = s[tid] - v;   // exclusive block offsets
}

__global__ void scan3_k() {
    int gid = blockIdx.x * 1024 + threadIdx.x;
    if (gid < SCAN_N) g_rowptr[gid] += g_bsum[blockIdx.x];
}

__global__ void cursor_k() {
    for (int i = blockIdx.x * blockDim.x + threadIdx.x; i < NT; i += gridDim.x * blockDim.x)
        g_cursor[i] = g_rowptr[i];
}

__global__ void scatter_k(const int* __restrict__ rows, const int* __restrict__ cols,
                          const float* __restrict__ vals) {
    for (int i = blockIdx.x * blockDim.x + threadIdx.x; i < NNZV; i += gridDim.x * blockDim.x) {
        int r = rows[i];
        int p = atomicAdd(&g_cursor[r], 1);
        g_col[p] = cols[i];
        g_val[p] = vals[i];
    }
}

// -------- SpMM: one warp per row, float2 per lane --------
// mode 0: src g_emb0 -> dst g_emb1      (layer 1)
// mode 1: src g_emb1 -> dst g_emb0      (layer 2)
// mode 2: src g_emb0 -> fused epilogue: out = (init + l1(g_emb1) + l2(g_emb0) + acc) * 0.25
__global__ void __launch_bounds__(256) spmm_k(int mode,
                                              const float* __restrict__ u,
                                              const float* __restrict__ it,
                                              float* __restrict__ out) {
    int gw = (blockIdx.x * blockDim.x + threadIdx.x) >> 5;
    int lane = threadIdx.x & 31;
    if (gw >= NT) return;

    const float* src = (mode == 1) ? g_emb1 : g_emb0;

    int start = g_rowptr[gw];
    int end   = g_rowptr[gw + 1];

    float2 acc = make_float2(0.f, 0.f);
    int j = start;
    // 4-way unroll for MLP on the gather loads
    for (; j + 4 <= end; j += 4) {
        int c0 = __ldg(&g_col[j + 0]);
        int c1 = __ldg(&g_col[j + 1]);
        int c2 = __ldg(&g_col[j + 2]);
        int c3 = __ldg(&g_col[j + 3]);
        float v0 = __ldg(&g_val[j + 0]);
        float v1 = __ldg(&g_val[j + 1]);
        float v2 = __ldg(&g_val[j + 2]);
        float v3 = __ldg(&g_val[j + 3]);
        float2 e0 = __ldg((const float2*)(src + (size_t)c0 * D) + lane);
        float2 e1 = __ldg((const float2*)(src + (size_t)c1 * D) + lane);
        float2 e2 = __ldg((const float2*)(src + (size_t)c2 * D) + lane);
        float2 e3 = __ldg((const float2*)(src + (size_t)c3 * D) + lane);
        acc.x += v0 * e0.x; acc.y += v0 * e0.y;
        acc.x += v1 * e1.x; acc.y += v1 * e1.y;
        acc.x += v2 * e2.x; acc.y += v2 * e2.y;
        acc.x += v3 * e3.x; acc.y += v3 * e3.y;
    }
    for (; j < end; j++) {
        int c = __ldg(&g_col[j]);
        float v = __ldg(&g_val[j]);
        float2 e = __ldg((const float2*)(src + (size_t)c * D) + lane);
        acc.x += v * e.x; acc.y += v * e.y;
    }

    int o = gw * D + lane * 2;
    if (mode == 0) {
        *(float2*)(g_emb1 + o) = acc;
    } else if (mode == 1) {
        *(float2*)(g_emb0 + o) = acc;
    } else {
        float2 l1 = *(const float2*)(g_emb1 + o);
        float2 l2 = *(const float2*)(g_emb0 + o);
        float2 e0;
        if (gw < NU) e0 = *(const float2*)(u + o);
        else         e0 = *(const float2*)(it + (size_t)(gw - NU) * D + lane * 2);
        float2 r;
        r.x = (e0.x + l1.x + l2.x + acc.x) * 0.25f;
        r.y = (e0.y + l1.y + l2.y + acc.y) * 0.25f;
        *(float2*)(out + o) = r;
    }
}

extern "C" void kernel_launch(void* const* d_in, const int* in_sizes, int n_in,
                              void* d_out, int out_size) {
    const float* user = (const float*)d_in[0];
    const float* item = (const float*)d_in[1];
    const int*   rows = (const int*)d_in[2];
    const int*   cols = (const int*)d_in[3];
    const float* vals = (const float*)d_in[4];
    float* out = (float*)d_out;

    (void)in_sizes; (void)n_in; (void)out_size;

    // CSR build
    init_k<<<4096, 256>>>((const float4*)user, (const float4*)item);
    zero_k<<<1024, 256>>>();
    hist_k<<<4096, 256>>>(rows);
    scan1_k<<<NB_SCAN, 1024>>>();
    scan2_k<<<1, 512>>>();
    scan3_k<<<NB_SCAN, 1024>>>();
    cursor_k<<<1024, 256>>>();
    scatter_k<<<4096, 256>>>(rows, cols, vals);

    // 3 SpMM layers, warp per row: 300000 warps -> 37500 blocks of 256
    const int blocks = (NT * 32 + 255) / 256;
    spmm_k<<<blocks, 256>>>(0, user, item, out);
    spmm_k<<<blocks, 256>>>(1, user, item, out);
    spmm_k<<<blocks, 256>>>(2, user, item, out);
}